// round 16
// baseline (speedup 1.0000x reference)
#include <cuda_runtime.h>

#define N_IMG 8
#define H 32
#define W 32
#define CIN 32
#define COUT 64
#define HO 30
#define WO 30
#define NPIX (N_IMG*HO*WO)       // 7200
#define PDIM (3*3*CIN)           // 288
#define HW (H*W)

typedef unsigned long long u64;
typedef unsigned int u32;

// ---------------------------------------------------------------------------
// Device-global scratch (no allocation allowed in kernel_launch)
// g_vq: NCHW, per element one ulonglong2 = { f32x2{vp,vp}, f32x2{vn,vn} }
//       index ((n*CIN+ci)*H + h)*W + w   (+64 pad for w+j overread)
// g_wpq: quarter-ordered packed weights:
//   item = ((qt*288 + k)*4 + cg), entries [2*item]=table1, [2*item+1]=table2
//   entry = { f32x2{ek[k][c0],ek[k][c0+1]}, f32x2{ek[k][c0+2],ek[k][c0+3]} }
//   c0 = qt*16 + cg*4
// ---------------------------------------------------------------------------
__device__ __align__(16) ulonglong2 g_vq[N_IMG*CIN*H*W + 64];
__device__ __align__(16) ulonglong2 g_wpq[2*PDIM*4*4];    // 9216 entries

#define TBLOCKS (N_IMG*H)        // 256 transpose blocks
#define WITEMS  (4*PDIM*4)       // 4608 weight items
#define WBLOCKS ((WITEMS + 1023)/1024)  // 5

#define SW_ENTRIES (PDIM*4*2)    // 2304 ulonglong2 = 36864 B per quarter
#define SMEM_BYTES (SW_ENTRIES*16)

// Two packed f32x2 multiplies, fold both ci-products into each u32 acc with
// one 3-input DPX max. Valid: all products are strictly positive finite
// floats (v >= 0.1, w = exp(k) > 0); positive IEEE floats order like u32.
__device__ __forceinline__ void mm3(u64 v0, u64 w0, u64 v1, u64 w1,
                                    u32& a0, u32& a1) {
    u32 p0lo, p0hi, p1lo, p1hi;
    asm("{\n\t"
        ".reg .b64 t0, t1;\n\t"
        "mul.rn.f32x2 t0, %4, %5;\n\t"
        "mul.rn.f32x2 t1, %6, %7;\n\t"
        "mov.b64 {%0, %1}, t0;\n\t"
        "mov.b64 {%2, %3}, t1;\n\t"
        "}"
        : "=r"(p0lo), "=r"(p0hi), "=r"(p1lo), "=r"(p1hi)
        : "l"(v0), "l"(w0), "l"(v1), "l"(w1));
    a0 = __vimax3_u32(a0, p0lo, p1lo);
    a1 = __vimax3_u32(a1, p0hi, p1hi);
}

__device__ __forceinline__ u64 packh(float lo, float hi) {
    return (u64)__float_as_uint(lo) | ((u64)__float_as_uint(hi) << 32);
}

// ---------------------------------------------------------------------------
// Fused prep:
//   blocks [0,TBLOCKS): clamp + NHWC -> NCHW splat-pair transpose via smem
//   blocks [TBLOCKS,+WBLOCKS): exp(weights) into quarter-ordered pairs
// ---------------------------------------------------------------------------
__global__ void prep(const float* __restrict__ x,
                     const float* __restrict__ k1,
                     const float* __restrict__ k2) {
    const int b = blockIdx.x;
    if (b < TBLOCKS) {
        __shared__ float tile[32][33];
        const int n = b >> 5;
        const int h = b & 31;
        {
            const int c = threadIdx.x;   // coalesced read (ci contiguous)
            const int w = threadIdx.y;
            tile[w][c] = x[(((n*H + h)*W + w)*CIN) + c];
        }
        __syncthreads();
        {
            const int w = threadIdx.x;   // coalesced write (w contiguous)
            const int c = threadIdx.y;
            const float v  = tile[w][c];
            const float vp = fmaxf(v, 0.1f);
            const float vn = fmaxf(-v, 0.1f);
            ulonglong2 e;
            e.x = packh(vp, vp);
            e.y = packh(vn, vn);
            g_vq[((n*CIN + c)*H + h)*W + w] = e;
        }
    } else {
        const int item = (b - TBLOCKS)*1024 + threadIdx.y*32 + threadIdx.x;
        if (item < WITEMS) {
            const int qt  = item / (PDIM*4);
            const int rem = item - qt*(PDIM*4);
            const int k   = rem >> 2;
            const int cg  = rem & 3;
            const int c0  = qt*16 + cg*4;
            const int base = k*COUT + c0;
            ulonglong2 e1, e2;
            e1.x = packh(expf(k1[base]),   expf(k1[base+1]));
            e1.y = packh(expf(k1[base+2]), expf(k1[base+3]));
            e2.x = packh(expf(k2[base]),   expf(k2[base+1]));
            e2.y = packh(expf(k2[base+2]), expf(k2[base+3]));
            g_wpq[item*2]     = e1;
            g_wpq[item*2 + 1] = e2;
        }
    }
}

// ---------------------------------------------------------------------------
// Main: CTA = 256 thr = 8 warps; blockIdx = (row 0..239)*4 + quarter.
// Warp wid: cg = wid&3 (4-cout group), cih = wid>>2 (ci half, 16 ci).
// Lane = pixel (w position). 16 u32 accs/lane, regs capped at 64 by
// __launch_bounds__(256,4) -> 4 CTAs/SM = 32 warps/SM (RF-exact).
// smem = 36.9KB: quarter weights only; v comes pre-splatted from gmem
// (L2-resident, LDG.128) -> no pack MOVs, no v smem.
// Per 2-ci warp-iter: 2 LDG.128 + 4 LDS.128 + 16 MUL2 + 16 VIMNMX3.
// 2-way ci combine through the (dead) weight smem region at the end.
// ---------------------------------------------------------------------------
__global__ void __launch_bounds__(256, 4)
morph_main(const float* __restrict__ bias, float* __restrict__ out) {
    extern __shared__ __align__(16) char smem[];
    ulonglong2* s_w = reinterpret_cast<ulonglong2*>(smem);
    u32*        s_r = reinterpret_cast<u32*>(smem);   // reused after loop

    const int tid  = threadIdx.x;
    const int wid  = tid >> 5;
    const int lane = tid & 31;         // pixel (w position)
    const int cg   = wid & 3;          // 4-cout group within quarter
    const int cih  = wid >> 2;         // ci half (16 ci)
    const int row  = blockIdx.x >> 2;  // 0..239
    const int qt   = blockIdx.x & 3;   // cout quarter
    const int n    = row / HO;
    const int ho   = row - n*HO;
    const int c0   = qt*16 + cg*4;     // global cout base (4 couts)

    // Stage this quarter's weights (contiguous 36864B)
    {
        const ulonglong2* __restrict__ src = g_wpq + qt*SW_ENTRIES;
        for (int idx = tid; idx < SW_ENTRIES; idx += 256)
            s_w[idx] = src[idx];
    }
    __syncthreads();

    // m[table: 11,12,21,22][cout 0..3]
    u32 m[4][4];
    #pragma unroll
    for (int t = 0; t < 4; t++)
        #pragma unroll
        for (int c = 0; c < 4; c++) m[t][c] = 0u;

    #pragma unroll 1
    for (int ij = 0; ij < 9; ij++) {
        const int i = ij / 3;
        const int j = ij - 3*i;
        // v: (n, ci = cih*16 + c, ho+i, lane+j); per-ci stride = HW
        const ulonglong2* __restrict__ vp =
            g_vq + ((n*CIN + cih*16)*H + (ho + i))*W + lane + j;
        // weights: entry ((k*4 + cg)*2), k = ij*32 + cih*16 + ci
        const ulonglong2* __restrict__ wp =
            s_w + ((ij*CIN + cih*16)*4 + cg)*2;

        #pragma unroll 2
        for (int c2 = 0; c2 < 8; c2++) {
            const ulonglong2 va  = __ldg(vp + (2*c2)*HW);     // {vxx, vnn}
            const ulonglong2 vb  = __ldg(vp + (2*c2+1)*HW);
            const ulonglong2 w1a = wp[(2*c2)*8];
            const ulonglong2 w2a = wp[(2*c2)*8 + 1];
            const ulonglong2 w1b = wp[(2*c2+1)*8];
            const ulonglong2 w2b = wp[(2*c2+1)*8 + 1];
            mm3(va.x, w1a.x, vb.x, w1b.x, m[0][0], m[0][1]);
            mm3(va.x, w1a.y, vb.x, w1b.y, m[0][2], m[0][3]);
            mm3(va.x, w2a.x, vb.x, w2b.x, m[1][0], m[1][1]);
            mm3(va.x, w2a.y, vb.x, w2b.y, m[1][2], m[1][3]);
            mm3(va.y, w1a.x, vb.y, w1b.x, m[2][0], m[2][1]);
            mm3(va.y, w1a.y, vb.y, w1b.y, m[2][2], m[2][3]);
            mm3(va.y, w2a.x, vb.y, w2b.x, m[3][0], m[3][1]);
            mm3(va.y, w2a.y, vb.y, w2b.y, m[3][2], m[3][3]);
        }
    }

    // 2-way ci-half combine in the (dead) weight smem region.
    __syncthreads();   // all warps done reading s_w
    if (cih == 1) {
        u32* dst = s_r + (cg*32 + lane)*16;
        #pragma unroll
        for (int t = 0; t < 4; t++)
            #pragma unroll
            for (int c = 0; c < 4; c++)
                dst[t*4 + c] = m[t][c];
    }
    __syncthreads();
    if (cih == 0 && lane < WO) {
        const u32* src = s_r + (cg*32 + lane)*16;
        #pragma unroll
        for (int t = 0; t < 4; t++)
            #pragma unroll
            for (int c = 0; c < 4; c++)
                m[t][c] = umax(m[t][c], src[t*4 + c]);

        const int q = (n*HO + ho)*WO + lane;
        const float4 bv = *reinterpret_cast<const float4*>(bias + c0);
        float4 res;
        res.x = __uint_as_float(m[0][0]) - __uint_as_float(m[1][0])
              - __uint_as_float(m[2][0]) + __uint_as_float(m[3][0]) + bv.x;
        res.y = __uint_as_float(m[0][1]) - __uint_as_float(m[1][1])
              - __uint_as_float(m[2][1]) + __uint_as_float(m[3][1]) + bv.y;
        res.z = __uint_as_float(m[0][2]) - __uint_as_float(m[1][2])
              - __uint_as_float(m[2][2]) + __uint_as_float(m[3][2]) + bv.z;
        res.w = __uint_as_float(m[0][3]) - __uint_as_float(m[1][3])
              - __uint_as_float(m[2][3]) + __uint_as_float(m[3][3]) + bv.w;
        *reinterpret_cast<float4*>(out + (size_t)q*COUT + c0) = res;
    }
}

// ---------------------------------------------------------------------------
extern "C" void kernel_launch(void* const* d_in, const int* in_sizes, int n_in,
                              void* d_out, int out_size) {
    const float* x    = (const float*)d_in[0];
    const float* k1   = (const float*)d_in[1];
    const float* k2   = (const float*)d_in[2];
    const float* bias = (const float*)d_in[3];
    float* out = (float*)d_out;

    cudaFuncSetAttribute(morph_main,
                         cudaFuncAttributeMaxDynamicSharedMemorySize,
                         SMEM_BYTES);

    prep<<<TBLOCKS + WBLOCKS, dim3(32,32)>>>(x, k1, k2);
    morph_main<<<240*4, 256, SMEM_BYTES>>>(bias, out);
}